// round 2
// baseline (speedup 1.0000x reference)
#include <cuda_runtime.h>

// Problem constants
#define HW   4096
#define CCH  64
#define CQD  8
#define NBAT 4

// Scratch (device globals — no allocation allowed)
__device__ float g_Q[NBAT * HW * CQD];   // [b][m][8]
__device__ float g_K[NBAT * HW * CQD];   // [b][n][8]
__device__ float g_V[NBAT * HW * CCH];   // [b][m][64]  (transposed V; prescaled by 1/denom[m] after denom_kernel)

// ---- packed f32x2 helpers ----
__device__ __forceinline__ unsigned long long pack2(float lo, float hi) {
    unsigned long long r;
    asm("mov.b64 %0, {%1, %2};" : "=l"(r) : "f"(lo), "f"(hi));
    return r;
}
__device__ __forceinline__ void unpack2(unsigned long long v, float& lo, float& hi) {
    asm("mov.b64 {%0, %1}, %2;" : "=f"(lo), "=f"(hi) : "l"(v));
}
__device__ __forceinline__ unsigned long long fma2(unsigned long long a,
                                                   unsigned long long b,
                                                   unsigned long long c) {
    unsigned long long d;
    asm("fma.rn.f32x2 %0, %1, %2, %3;" : "=l"(d) : "l"(a), "l"(b), "l"(c));
    return d;
}
__device__ __forceinline__ unsigned long long mul2(unsigned long long a,
                                                   unsigned long long b) {
    unsigned long long d;
    asm("mul.rn.f32x2 %0, %1, %2;" : "=l"(d) : "l"(a), "l"(b));
    return d;
}

// ============================================================================
// Kernel 1: QKV projections (1x1 convs).  One thread per pixel.
//   Q[b][n][o] = sum_c Wq[o][c] * x[b][c][n] + bq[o]   (o < 8)
//   K likewise; V[b][n][o] = sum_c Wv[o][c] * x[b][c][n] + bv[o]  (o < 64)
// ============================================================================
__global__ __launch_bounds__(128) void qkv_kernel(
    const float* __restrict__ x,
    const float* __restrict__ Wq, const float* __restrict__ bq,
    const float* __restrict__ Wk, const float* __restrict__ bk,
    const float* __restrict__ Wv, const float* __restrict__ bv)
{
    __shared__ float WqT[CCH][CQD];   // [c][o]
    __shared__ float WkT[CCH][CQD];   // [c][o]
    __shared__ float WvT[CCH][CCH];   // [c][o]

    const int t = threadIdx.x;
    for (int i = t; i < CCH * CQD; i += 128) {
        int o = i / CCH, c = i % CCH;
        WqT[c][o] = Wq[i];
        WkT[c][o] = Wk[i];
    }
    for (int i = t; i < CCH * CCH; i += 128) {
        int o = i / CCH, c = i % CCH;
        WvT[c][o] = Wv[i];
    }
    __syncthreads();

    const int b = blockIdx.y;
    const int n = blockIdx.x * 128 + t;
    const float* xp = x + ((size_t)b * CCH) * HW + n;

    unsigned long long qa[CQD / 2], ka[CQD / 2], va[CCH / 2];
#pragma unroll
    for (int i = 0; i < CQD / 2; i++) {
        qa[i] = pack2(bq[2 * i], bq[2 * i + 1]);
        ka[i] = pack2(bk[2 * i], bk[2 * i + 1]);
    }
#pragma unroll
    for (int i = 0; i < CCH / 2; i++) va[i] = pack2(bv[2 * i], bv[2 * i + 1]);

#pragma unroll 4
    for (int c = 0; c < CCH; c++) {
        float xv = xp[(size_t)c * HW];       // coalesced across lanes
        unsigned long long xx = pack2(xv, xv);
        const unsigned long long* wq2 = (const unsigned long long*)WqT[c];
        const unsigned long long* wk2 = (const unsigned long long*)WkT[c];
        const unsigned long long* wv2 = (const unsigned long long*)WvT[c];
#pragma unroll
        for (int i = 0; i < CQD / 2; i++) {
            qa[i] = fma2(xx, wq2[i], qa[i]);
            ka[i] = fma2(xx, wk2[i], ka[i]);
        }
#pragma unroll
        for (int i = 0; i < CCH / 2; i++) va[i] = fma2(xx, wv2[i], va[i]);
    }

    unsigned long long* Qp = (unsigned long long*)(g_Q + ((size_t)b * HW + n) * CQD);
    unsigned long long* Kp = (unsigned long long*)(g_K + ((size_t)b * HW + n) * CQD);
    unsigned long long* Vp = (unsigned long long*)(g_V + ((size_t)b * HW + n) * CCH);
#pragma unroll
    for (int i = 0; i < CQD / 2; i++) { Qp[i] = qa[i]; Kp[i] = ka[i]; }
#pragma unroll
    for (int i = 0; i < CCH / 2; i++) Vp[i] = va[i];
}

// ============================================================================
// Kernel 2: denominators of the (row-)softmax, then prescale V in place.
//   denom[m] = sum_j exp(Q[m] . K[j]);   V'[m][:] = V[m][:] / denom[m]
//   One thread per key m; K chunks of 256 staged in smem (broadcast reads).
// ============================================================================
__global__ __launch_bounds__(256) void denom_kernel()
{
    __shared__ float Ks[256 * CQD];    // 8 KB

    const int t = threadIdx.x;
    const int b = blockIdx.y;
    const int m = blockIdx.x * 256 + t;

    const float4* Qr = (const float4*)(g_Q + ((size_t)b * HW + m) * CQD);
    const float4 q0 = Qr[0];
    const float4 q1 = Qr[1];

    const float4* Kg = (const float4*)(g_K + (size_t)b * HW * CQD);
    float4* Ks4 = (float4*)Ks;

    float denom = 0.0f;
    for (int n0 = 0; n0 < HW; n0 += 256) {
        __syncthreads();
        Ks4[t]       = Kg[n0 * 2 + t];
        Ks4[t + 256] = Kg[n0 * 2 + t + 256];
        __syncthreads();
#pragma unroll 4
        for (int j = 0; j < 256; j++) {
            const float4 k0 = Ks4[2 * j];
            const float4 k1 = Ks4[2 * j + 1];
            float s = ((q0.x * k0.x + q0.y * k0.y) + (q0.z * k0.z + q0.w * k0.w))
                    + ((q1.x * k1.x + q1.y * k1.y) + (q1.z * k1.z + q1.w * k1.w));
            denom += __expf(s);        // logits bounded ~|3|: no max-subtraction needed
        }
    }

    // prescale this key's V row by 1/denom (folds normalization out of kernel 3)
    const float inv = 1.0f / denom;
    const unsigned long long iv = pack2(inv, inv);
    unsigned long long* Vp = (unsigned long long*)(g_V + ((size_t)b * HW + m) * CCH);
#pragma unroll
    for (int i = 0; i < CCH / 2; i++) Vp[i] = mul2(iv, Vp[i]);
}

// ============================================================================
// Kernel 3: aggregation.  out[c][n] = gamma * sum_m exp(Q[m].K[n]) * V'[c][m] + x
//   Block: 256 threads = 128 output pixels x 2 channel-halves.
//   The per-pixel "query" vector is K[n]; keys are Q[m]; V' is prescaled.
// ============================================================================
__global__ __launch_bounds__(256) void attn_kernel(
    const float* __restrict__ x,
    const float* __restrict__ gamma,
    float* __restrict__ out)
{
    __shared__ float Qs[128 * CQD];    // [m][8]   4 KB
    __shared__ float Vs[128 * CCH];    // [m][64] 32 KB

    const int t  = threadIdx.x;
    const int b  = blockIdx.y;
    const int qi = t & 127;            // output pixel within block
    const int h  = t >> 7;             // channel half (0: c 0..31, 1: c 32..63)
    const int n  = blockIdx.x * 128 + qi;

    // this output pixel's vector is K[n]
    const float4* Kr = (const float4*)(g_K + ((size_t)b * HW + n) * CQD);
    const float4 k0 = Kr[0];
    const float4 k1 = Kr[1];

    unsigned long long acc[16];        // 32 fp32 channels, packed
#pragma unroll
    for (int i = 0; i < 16; i++) acc[i] = 0ULL;

    const float4* Qg = (const float4*)(g_Q + (size_t)b * HW * CQD);
    const float4* Vg = (const float4*)(g_V + (size_t)b * HW * CCH);
    float4* Qs4 = (float4*)Qs;
    float4* Vs4 = (float4*)Vs;

    for (int m0 = 0; m0 < HW; m0 += 128) {
        __syncthreads();
        // Q chunk: 128 keys * 8 floats = 256 float4 (1 per thread)
        Qs4[t] = Qg[m0 * 2 + t];
        // V chunk: 128 keys * 64 floats = 2048 float4 (8 per thread)
#pragma unroll
        for (int j = 0; j < 8; j++)
            Vs4[t + j * 256] = Vg[m0 * 16 + t + j * 256];
        __syncthreads();

#pragma unroll 2
        for (int m = 0; m < 128; m++) {
            const float4 a0 = Qs4[m * 2];
            const float4 a1 = Qs4[m * 2 + 1];
            // balanced-tree dot product (depth 3 FMA chains)
            float s = ((a0.x * k0.x + a0.y * k0.y) + (a0.z * k0.z + a0.w * k0.w))
                    + ((a1.x * k1.x + a1.y * k1.y) + (a1.z * k1.z + a1.w * k1.w));
            float p = __expf(s);       // V already carries 1/denom[m]
            unsigned long long pp = pack2(p, p);
            const ulonglong2* vr = (const ulonglong2*)(Vs + m * CCH + h * 32);
#pragma unroll
            for (int j = 0; j < 8; j++) {
                ulonglong2 vv = vr[j];                 // LDS.128, warp-broadcast
                acc[2 * j]     = fma2(pp, vv.x, acc[2 * j]);
                acc[2 * j + 1] = fma2(pp, vv.y, acc[2 * j + 1]);
            }
        }
    }

    // epilogue: scale by gamma, add residual. Coalesced per channel.
    const float scale = gamma[0];
    const float* xb = x   + ((size_t)b * CCH + h * 32) * HW + n;
    float*       ob = out + ((size_t)b * CCH + h * 32) * HW + n;
#pragma unroll
    for (int j = 0; j < 16; j++) {
        float lo, hi;
        unpack2(acc[j], lo, hi);
        ob[(size_t)(2 * j)     * HW] = lo * scale + xb[(size_t)(2 * j)     * HW];
        ob[(size_t)(2 * j + 1) * HW] = hi * scale + xb[(size_t)(2 * j + 1) * HW];
    }
}

// ============================================================================
extern "C" void kernel_launch(void* const* d_in, const int* in_sizes, int n_in,
                              void* d_out, int out_size)
{
    const float* x     = (const float*)d_in[0];
    const float* Wq    = (const float*)d_in[1];
    const float* bq    = (const float*)d_in[2];
    const float* Wk    = (const float*)d_in[3];
    const float* bk    = (const float*)d_in[4];
    const float* Wv    = (const float*)d_in[5];
    const float* bv    = (const float*)d_in[6];
    const float* gamma = (const float*)d_in[7];
    float* out = (float*)d_out;

    qkv_kernel<<<dim3(HW / 128, NBAT), 128>>>(x, Wq, bq, Wk, bk, Wv, bv);
    denom_kernel<<<dim3(HW / 256, NBAT), 256>>>();
    attn_kernel<<<dim3(HW / 128, NBAT), 256>>>(x, gamma, out);
}

// round 4
// speedup vs baseline: 3.2997x; 3.2997x over previous
#include <cuda_runtime.h>
#include <cuda_bf16.h>
#include <cstdint>

// Problem constants
#define HW   4096
#define CCH  64
#define CQD  8
#define NBAT 4
#define NSPL 4          // denom j-split (deterministic partials, no atomics)

// Scratch (device globals — no allocation allowed)
__device__ float         g_Q[NBAT * HW * CQD];        // [b][m][8]
__device__ float         g_K[NBAT * HW * CQD];        // [b][n][8]
__device__ __nv_bfloat16 g_Vh[NBAT * CCH * HW];       // [b][c][n]  bf16, channel-major
__device__ float         g_dpart[NSPL * NBAT * HW];   // per-split softmax denominators

// ---------------------------------------------------------------------------
// helpers
// ---------------------------------------------------------------------------
__device__ __forceinline__ unsigned long long pack2(float lo, float hi) {
    unsigned long long r;
    asm("mov.b64 %0, {%1, %2};" : "=l"(r) : "f"(lo), "f"(hi));
    return r;
}
__device__ __forceinline__ void unpack2(unsigned long long v, float& lo, float& hi) {
    asm("mov.b64 {%0, %1}, %2;" : "=f"(lo), "=f"(hi) : "l"(v));
}
__device__ __forceinline__ unsigned long long fma2(unsigned long long a,
                                                   unsigned long long b,
                                                   unsigned long long c) {
    unsigned long long d;
    asm("fma.rn.f32x2 %0, %1, %2, %3;" : "=l"(d) : "l"(a), "l"(b), "l"(c));
    return d;
}
__device__ __forceinline__ uint32_t smem_u32(const void* p) {
    uint32_t a;
    asm("{ .reg .u64 t; cvta.to.shared.u64 t, %1; cvt.u32.u64 %0, t; }" : "=r"(a) : "l"(p));
    return a;
}
__device__ __forceinline__ void ldsm4(uint32_t* r, uint32_t addr) {
    asm volatile("ldmatrix.sync.aligned.m8n8.x4.shared.b16 {%0,%1,%2,%3}, [%4];"
                 : "=r"(r[0]), "=r"(r[1]), "=r"(r[2]), "=r"(r[3]) : "r"(addr));
}
__device__ __forceinline__ void mma16816(float* d, const uint32_t* a,
                                         uint32_t b0, uint32_t b1) {
    asm volatile("mma.sync.aligned.m16n8k16.row.col.f32.bf16.bf16.f32 "
                 "{%0,%1,%2,%3}, {%4,%5,%6,%7}, {%8,%9}, {%0,%1,%2,%3};"
                 : "+f"(d[0]), "+f"(d[1]), "+f"(d[2]), "+f"(d[3])
                 : "r"(a[0]), "r"(a[1]), "r"(a[2]), "r"(a[3]), "r"(b0), "r"(b1));
}

// ---------------------------------------------------------------------------
// Kernel 1: QKV projections (1x1 convs).  One thread per pixel.
// ---------------------------------------------------------------------------
__global__ __launch_bounds__(128) void qkv_kernel(
    const float* __restrict__ x,
    const float* __restrict__ Wq, const float* __restrict__ bq,
    const float* __restrict__ Wk, const float* __restrict__ bk,
    const float* __restrict__ Wv, const float* __restrict__ bv)
{
    __shared__ float WqT[CCH][CQD];
    __shared__ float WkT[CCH][CQD];
    __shared__ float WvT[CCH][CCH];

    const int t = threadIdx.x;
    for (int i = t; i < CCH * CQD; i += 128) {
        int o = i / CCH, c = i % CCH;
        WqT[c][o] = Wq[i];
        WkT[c][o] = Wk[i];
    }
    for (int i = t; i < CCH * CCH; i += 128) {
        int o = i / CCH, c = i % CCH;
        WvT[c][o] = Wv[i];
    }
    __syncthreads();

    const int b = blockIdx.y;
    const int n = blockIdx.x * 128 + t;
    const float* xp = x + ((size_t)b * CCH) * HW + n;

    unsigned long long qa[CQD / 2], ka[CQD / 2], va[CCH / 2];
#pragma unroll
    for (int i = 0; i < CQD / 2; i++) {
        qa[i] = pack2(bq[2 * i], bq[2 * i + 1]);
        ka[i] = pack2(bk[2 * i], bk[2 * i + 1]);
    }
#pragma unroll
    for (int i = 0; i < CCH / 2; i++) va[i] = pack2(bv[2 * i], bv[2 * i + 1]);

#pragma unroll 4
    for (int c = 0; c < CCH; c++) {
        float xv = xp[(size_t)c * HW];
        unsigned long long xx = pack2(xv, xv);
        const unsigned long long* wq2 = (const unsigned long long*)WqT[c];
        const unsigned long long* wk2 = (const unsigned long long*)WkT[c];
        const unsigned long long* wv2 = (const unsigned long long*)WvT[c];
#pragma unroll
        for (int i = 0; i < CQD / 2; i++) {
            qa[i] = fma2(xx, wq2[i], qa[i]);
            ka[i] = fma2(xx, wk2[i], ka[i]);
        }
#pragma unroll
        for (int i = 0; i < CCH / 2; i++) va[i] = fma2(xx, wv2[i], va[i]);
    }

    unsigned long long* Qp = (unsigned long long*)(g_Q + ((size_t)b * HW + n) * CQD);
    unsigned long long* Kp = (unsigned long long*)(g_K + ((size_t)b * HW + n) * CQD);
#pragma unroll
    for (int i = 0; i < CQD / 2; i++) { Qp[i] = qa[i]; Kp[i] = ka[i]; }

    // V -> bf16, channel-major [b][c][n] (coalesced across lanes per channel)
    __nv_bfloat16* Vp = g_Vh + (size_t)b * CCH * HW + n;
#pragma unroll
    for (int i = 0; i < CCH / 2; i++) {
        float lo, hi;
        unpack2(va[i], lo, hi);
        Vp[(size_t)(2 * i)     * HW] = __float2bfloat16(lo);
        Vp[(size_t)(2 * i + 1) * HW] = __float2bfloat16(hi);
    }
}

// ---------------------------------------------------------------------------
// Kernel 2: softmax denominators (partial, deterministic split over keys j)
//   g_dpart[s][b][m] = sum_{j in split s} exp(Q[m].K[j])
// ---------------------------------------------------------------------------
__global__ __launch_bounds__(256) void denom_kernel()
{
    __shared__ float Ks[256 * CQD];

    const int t = threadIdx.x;
    const int b = blockIdx.z;
    const int s = blockIdx.y;
    const int m = blockIdx.x * 256 + t;
    const int j0 = s * (HW / NSPL);

    const float4* Qr = (const float4*)(g_Q + ((size_t)b * HW + m) * CQD);
    const float4 q0 = Qr[0];
    const float4 q1 = Qr[1];

    const float4* Kg = (const float4*)(g_K + (size_t)b * HW * CQD);
    float4* Ks4 = (float4*)Ks;

    float denom = 0.0f;
    for (int jc = 0; jc < HW / NSPL; jc += 256) {
        __syncthreads();
        Ks4[t]       = Kg[(j0 + jc) * 2 + t];
        Ks4[t + 256] = Kg[(j0 + jc) * 2 + t + 256];
        __syncthreads();
#pragma unroll 4
        for (int j = 0; j < 256; j++) {
            const float4 k0 = Ks4[2 * j];
            const float4 k1 = Ks4[2 * j + 1];
            float sc = ((q0.x * k0.x + q0.y * k0.y) + (q0.z * k0.z + q0.w * k0.w))
                     + ((q1.x * k1.x + q1.y * k1.y) + (q1.z * k1.z + q1.w * k1.w));
            denom += __expf(sc);   // logits bounded ~|3|
        }
    }
    g_dpart[((size_t)s * NBAT + b) * HW + m] = denom;
}

// ---------------------------------------------------------------------------
// Kernel 3: tensor-core aggregation via mma.sync (bf16 HMMA).
//   D[n][c] = sum_m P'[n][m] * V[c][m],  P'[n][m] = exp(Q[m].K[n]) * invd[m]
// 512 threads: 16 warps compute P' tile; warps 0-7 run MMA (16 rows each),
// fp32 accumulators live in registers across all 32 key chunks.
// SMEM (dynamic, byte offsets):
//   P  [128][136 bf16] (272B rows)  0      .. 34816   (reused as f32 out-stage)
//   V  [ 64][136 bf16]              34816  .. 52224
//   Q  [128][8] f32                 52224  .. 56320
//   K  [128][8] f32                 56320  .. 60416
//   invd [128] f32                  60416  .. 60928
// ---------------------------------------------------------------------------
#define PSTR    272
#define SM_P    0
#define SM_V    34816
#define SM_Q    52224
#define SM_K    56320
#define SM_INVD 60416
#define SM_BYTES 60928
#define OSTR    65      // f32 words per row in output staging

__global__ __launch_bounds__(512) void attn_kernel(
    const float* __restrict__ x,
    const float* __restrict__ gamma,
    float* __restrict__ out)
{
    extern __shared__ uint8_t sm[];
    const uint32_t smb = smem_u32(sm);

    const int t = threadIdx.x;
    const int w = t >> 5;
    const int l = t & 31;
    const int b = blockIdx.y;
    const int n0 = blockIdx.x * 128;

    float4* Qs4   = (float4*)(sm + SM_Q);
    float4* Ks4   = (float4*)(sm + SM_K);
    float*  invds = (float*)(sm + SM_INVD);

    // stage K rows for this block (once)
    const float4* Kg = (const float4*)(g_K + (size_t)b * HW * CQD);
    if (t < 256) Ks4[t] = Kg[n0 * 2 + t];

    const float4* Qg  = (const float4*)(g_Q + (size_t)b * HW * CQD);
    const uint4*  Vg4 = (const uint4*)(g_Vh + (size_t)b * CCH * HW);

    // MMA accumulators (warps 0-7): warp w owns pixel rows 16w..16w+15,
    // acc[j] = 16x8 D-frag for channels 8j..8j+7.
    float acc[8][4];
#pragma unroll
    for (int j = 0; j < 8; j++)
#pragma unroll
        for (int i = 0; i < 4; i++) acc[j][i] = 0.0f;

    // P-compute roles: warp w writes pixel rows 8w..8w+7; lane l owns
    // m columns {2l, 2l+1, 64+2l, 65+2l}.
    for (int chunk = 0; chunk < HW / 128; chunk++) {
        const int m0 = chunk * 128;
        __syncthreads();                         // prior MMA done with P/V
        // stage Q chunk [128][8]
        if (t < 256) Qs4[t] = Qg[m0 * 2 + t];
        // stage V chunk [64][128] bf16 (row pad 272B)
#pragma unroll
        for (int jj = 0; jj < 2; jj++) {
            int i = t + jj * 512;                // 0..1023
            int row = i >> 4, c16 = i & 15;
            uint4 v = Vg4[(size_t)row * (HW / 8) + (m0 >> 3) + c16];
            *(uint4*)(sm + SM_V + row * PSTR + c16 * 16) = v;
        }
        if (t < 128) {
            float d = g_dpart[(size_t)b * HW + m0 + t]
                    + g_dpart[((size_t)NBAT + b) * HW + m0 + t]
                    + g_dpart[((size_t)2 * NBAT + b) * HW + m0 + t]
                    + g_dpart[((size_t)3 * NBAT + b) * HW + m0 + t];
            invds[t] = __fdividef(1.0f, d);
        }
        __syncthreads();

        // ---- P' tile compute ----
        const float4 qa0 = Qs4[4 * l],       qa1 = Qs4[4 * l + 1];
        const float4 qb0 = Qs4[4 * l + 2],   qb1 = Qs4[4 * l + 3];
        const float4 qc0 = Qs4[128 + 4 * l], qc1 = Qs4[128 + 4 * l + 1];
        const float4 qd0 = Qs4[130 + 4 * l], qd1 = Qs4[130 + 4 * l + 1];
        const float ia = invds[2 * l],      ib = invds[2 * l + 1];
        const float ic = invds[64 + 2 * l], id = invds[65 + 2 * l];
        uint8_t* prow = sm + SM_P + (8 * w) * PSTR + 4 * l;
#pragma unroll
        for (int r = 0; r < 8; r++) {
            const int n = 8 * w + r;
            const float4 k0 = Ks4[2 * n];
            const float4 k1 = Ks4[2 * n + 1];
            float sa = ((qa0.x*k0.x + qa0.y*k0.y) + (qa0.z*k0.z + qa0.w*k0.w))
                     + ((qa1.x*k1.x + qa1.y*k1.y) + (qa1.z*k1.z + qa1.w*k1.w));
            float sb = ((qb0.x*k0.x + qb0.y*k0.y) + (qb0.z*k0.z + qb0.w*k0.w))
                     + ((qb1.x*k1.x + qb1.y*k1.y) + (qb1.z*k1.z + qb1.w*k1.w));
            float sc = ((qc0.x*k0.x + qc0.y*k0.y) + (qc0.z*k0.z + qc0.w*k0.w))
                     + ((qc1.x*k1.x + qc1.y*k1.y) + (qc1.z*k1.z + qc1.w*k1.w));
            float sd = ((qd0.x*k0.x + qd0.y*k0.y) + (qd0.z*k0.z + qd0.w*k0.w))
                     + ((qd1.x*k1.x + qd1.y*k1.y) + (qd1.z*k1.z + qd1.w*k1.w));
            float pa = __expf(sa) * ia;
            float pb = __expf(sb) * ib;
            float pc = __expf(sc) * ic;
            float pd = __expf(sd) * id;
            uint32_t w0, w1;
            asm("cvt.rn.satfinite.bf16x2.f32 %0, %1, %2;" : "=r"(w0) : "f"(pb), "f"(pa));
            asm("cvt.rn.satfinite.bf16x2.f32 %0, %1, %2;" : "=r"(w1) : "f"(pd), "f"(pc));
            *(uint32_t*)(prow + r * PSTR)       = w0;   // m = 2l, 2l+1
            *(uint32_t*)(prow + r * PSTR + 128) = w1;   // m = 64+2l, 65+2l
        }
        __syncthreads();

        // ---- MMA: warps 0-7, 16 pixel rows each, k = 128 in 8 steps ----
        if (w < 8) {
            const uint32_t arow = smb + SM_P + (16 * w + (l & 15)) * PSTR + ((l >> 4) * 16);
            const uint32_t brow = smb + SM_V + (l & 15) * PSTR + ((l >> 4) * 16);
#pragma unroll
            for (int kk = 0; kk < 8; kk++) {
                uint32_t a[4];
                ldsm4(a, arow + kk * 32);
#pragma unroll
                for (int nt = 0; nt < 4; nt++) {
                    uint32_t bb[4];
                    ldsm4(bb, brow + nt * 16 * PSTR + kk * 32);
                    mma16816(acc[2 * nt],     a, bb[0], bb[2]);
                    mma16816(acc[2 * nt + 1], a, bb[1], bb[3]);
                }
            }
        }
    }

    // ---- epilogue: stage D through smem for coalesced writes ----
    __syncthreads();
    float* sD = (float*)(sm + SM_P);             // [128][OSTR]
    if (w < 8) {
        const int g = l >> 2, tg = l & 3;
#pragma unroll
        for (int j = 0; j < 8; j++) {
            const int c = j * 8 + 2 * tg;
            sD[(16 * w + g) * OSTR + c]         = acc[j][0];
            sD[(16 * w + g) * OSTR + c + 1]     = acc[j][1];
            sD[(16 * w + g + 8) * OSTR + c]     = acc[j][2];
            sD[(16 * w + g + 8) * OSTR + c + 1] = acc[j][3];
        }
    }
    __syncthreads();

    const float gm = gamma[0];
#pragma unroll
    for (int i = t; i < 128 * CCH; i += 512) {
        const int c = i >> 7, n = i & 127;
        const size_t gi = (size_t)b * CCH * HW + (size_t)c * HW + n0 + n;
        out[gi] = gm * sD[n * OSTR + c] + x[gi];
    }
}

// ---------------------------------------------------------------------------
extern "C" void kernel_launch(void* const* d_in, const int* in_sizes, int n_in,
                              void* d_out, int out_size)
{
    const float* x     = (const float*)d_in[0];
    const float* Wq    = (const float*)d_in[1];
    const float* bq    = (const float*)d_in[2];
    const float* Wk    = (const float*)d_in[3];
    const float* bk    = (const float*)d_in[4];
    const float* Wv    = (const float*)d_in[5];
    const float* bv    = (const float*)d_in[6];
    const float* gamma = (const float*)d_in[7];
    float* out = (float*)d_out;

    cudaFuncSetAttribute(attn_kernel, cudaFuncAttributeMaxDynamicSharedMemorySize, SM_BYTES);

    qkv_kernel<<<dim3(HW / 128, NBAT), 128>>>(x, Wq, bq, Wk, bk, Wv, bv);
    denom_kernel<<<dim3(HW / 256, NSPL, NBAT), 256>>>();
    attn_kernel<<<dim3(HW / 128, NBAT), 512, SM_BYTES>>>(x, gamma, out);
}

// round 5
// speedup vs baseline: 7.0281x; 2.1299x over previous
#include <cuda_runtime.h>
#include <cuda_fp16.h>
#include <cstdint>

// Problem constants
#define HW   4096
#define CCH  64
#define CQD  8
#define NBAT 4
#define NSPL 4          // denom j-split (deterministic partials, no atomics)

// Scratch (device globals — no allocation allowed)
__device__ __half g_Qh[NBAT * HW * CQD];      // [b][m][8] fp16
__device__ __half g_Kh[NBAT * HW * CQD];      // [b][n][8] fp16
__device__ __half g_Vh[NBAT * CCH * HW];      // [b][c][m] fp16 (vscale: *= 4096/denom[m])
__device__ float  g_dpart[NSPL * NBAT * HW];  // per-split softmax denominators

// ---------------------------------------------------------------------------
// helpers
// ---------------------------------------------------------------------------
__device__ __forceinline__ unsigned long long pack2(float lo, float hi) {
    unsigned long long r;
    asm("mov.b64 %0, {%1, %2};" : "=l"(r) : "f"(lo), "f"(hi));
    return r;
}
__device__ __forceinline__ void unpack2(unsigned long long v, float& lo, float& hi) {
    asm("mov.b64 {%0, %1}, %2;" : "=f"(lo), "=f"(hi) : "l"(v));
}
__device__ __forceinline__ unsigned long long fma2(unsigned long long a,
                                                   unsigned long long b,
                                                   unsigned long long c) {
    unsigned long long d;
    asm("fma.rn.f32x2 %0, %1, %2, %3;" : "=l"(d) : "l"(a), "l"(b), "l"(c));
    return d;
}
__device__ __forceinline__ uint32_t smem_u32(const void* p) {
    uint32_t a;
    asm("{ .reg .u64 t; cvta.to.shared.u64 t, %1; cvt.u32.u64 %0, t; }" : "=r"(a) : "l"(p));
    return a;
}
__device__ __forceinline__ void ldsm2(uint32_t* r, uint32_t addr) {
    asm volatile("ldmatrix.sync.aligned.m8n8.x2.shared.b16 {%0,%1}, [%2];"
                 : "=r"(r[0]), "=r"(r[1]) : "r"(addr));
}
__device__ __forceinline__ void ldsm4(uint32_t* r, uint32_t addr) {
    asm volatile("ldmatrix.sync.aligned.m8n8.x4.shared.b16 {%0,%1,%2,%3}, [%4];"
                 : "=r"(r[0]), "=r"(r[1]), "=r"(r[2]), "=r"(r[3]) : "r"(addr));
}
// S-tile: D(16x8) = A(16x8=K/Q rows) x B(8x8), fp16 in, fp32 acc
__device__ __forceinline__ void mma8(float& d0, float& d1, float& d2, float& d3,
                                     const uint32_t* a, uint32_t b) {
    asm volatile("mma.sync.aligned.m16n8k8.row.col.f32.f16.f16.f32 "
                 "{%0,%1,%2,%3}, {%4,%5}, {%6}, {%0,%1,%2,%3};"
                 : "+f"(d0), "+f"(d1), "+f"(d2), "+f"(d3)
                 : "r"(a[0]), "r"(a[1]), "r"(b));
}
// P@V: D(16x8) += A(16x16) x B(16x8)
__device__ __forceinline__ void mma16(float* d, const uint32_t* a,
                                      uint32_t b0, uint32_t b1) {
    asm volatile("mma.sync.aligned.m16n8k16.row.col.f32.f16.f16.f32 "
                 "{%0,%1,%2,%3}, {%4,%5,%6,%7}, {%8,%9}, {%0,%1,%2,%3};"
                 : "+f"(d[0]), "+f"(d[1]), "+f"(d[2]), "+f"(d[3])
                 : "r"(a[0]), "r"(a[1]), "r"(a[2]), "r"(a[3]), "r"(b0), "r"(b1));
}
__device__ __forceinline__ uint32_t cvt_h2(float lo, float hi) {
    uint32_t r;
    asm("cvt.rn.f16x2.f32 %0, %1, %2;" : "=r"(r) : "f"(hi), "f"(lo));
    return r;
}

// ---------------------------------------------------------------------------
// Kernel 1: QKV projections.  4 threads per pixel (h = channel group).
// ---------------------------------------------------------------------------
__global__ __launch_bounds__(512) void qkv_kernel(
    const float* __restrict__ x,
    const float* __restrict__ Wq, const float* __restrict__ bq,
    const float* __restrict__ Wk, const float* __restrict__ bk,
    const float* __restrict__ Wv, const float* __restrict__ bv)
{
    __shared__ float WqT[CCH][CQD];
    __shared__ float WkT[CCH][CQD];
    __shared__ float WvT[CCH][CCH];

    const int t = threadIdx.x;
    for (int i = t; i < CCH * CQD; i += 512) {
        int o = i / CCH, c = i % CCH;
        WqT[c][o] = Wq[i];
        WkT[c][o] = Wk[i];
    }
    for (int i = t; i < CCH * CCH; i += 512) {
        int o = i / CCH, c = i % CCH;
        WvT[c][o] = Wv[i];
    }
    __syncthreads();

    const int b  = blockIdx.y;
    const int px = t & 127;
    const int h  = t >> 7;             // warp-uniform channel group
    const int n  = blockIdx.x * 128 + px;
    const float* xp = x + (size_t)b * CCH * HW + n;

    unsigned long long va[8], qa[4], ka[4];
#pragma unroll
    for (int i = 0; i < 8; i++) va[i] = pack2(bv[16 * h + 2 * i], bv[16 * h + 2 * i + 1]);
    if (h == 0) {
#pragma unroll
        for (int i = 0; i < 4; i++) qa[i] = pack2(bq[2 * i], bq[2 * i + 1]);
    }
    if (h == 1) {
#pragma unroll
        for (int i = 0; i < 4; i++) ka[i] = pack2(bk[2 * i], bk[2 * i + 1]);
    }

#pragma unroll 4
    for (int c = 0; c < CCH; c++) {
        float xv = xp[(size_t)c * HW];
        unsigned long long xx = pack2(xv, xv);
        const unsigned long long* wv2 = (const unsigned long long*)&WvT[c][16 * h];
#pragma unroll
        for (int i = 0; i < 8; i++) va[i] = fma2(xx, wv2[i], va[i]);
        if (h == 0) {
            const unsigned long long* wq2 = (const unsigned long long*)WqT[c];
#pragma unroll
            for (int i = 0; i < 4; i++) qa[i] = fma2(xx, wq2[i], qa[i]);
        }
        if (h == 1) {
            const unsigned long long* wk2 = (const unsigned long long*)WkT[c];
#pragma unroll
            for (int i = 0; i < 4; i++) ka[i] = fma2(xx, wk2[i], ka[i]);
        }
    }

    // V -> fp16 channel-major (coalesced across lanes per channel)
    __half* Vp = g_Vh + ((size_t)b * CCH + 16 * h) * HW + n;
#pragma unroll
    for (int i = 0; i < 8; i++) {
        float lo, hi;
        unpack2(va[i], lo, hi);
        Vp[(size_t)(2 * i) * HW]     = __float2half(lo);
        Vp[(size_t)(2 * i + 1) * HW] = __float2half(hi);
    }
    if (h == 0) {
        uint32_t u[4];
#pragma unroll
        for (int i = 0; i < 4; i++) {
            float lo, hi;
            unpack2(qa[i], lo, hi);
            u[i] = cvt_h2(lo, hi);
        }
        *(uint4*)(g_Qh + ((size_t)b * HW + n) * CQD) = make_uint4(u[0], u[1], u[2], u[3]);
    }
    if (h == 1) {
        uint32_t u[4];
#pragma unroll
        for (int i = 0; i < 4; i++) {
            float lo, hi;
            unpack2(ka[i], lo, hi);
            u[i] = cvt_h2(lo, hi);
        }
        *(uint4*)(g_Kh + ((size_t)b * HW + n) * CQD) = make_uint4(u[0], u[1], u[2], u[3]);
    }
}

// ---------------------------------------------------------------------------
// Kernel 2: softmax denominators via MMA scores.
//   Block owns 128 m (Q rows); split s covers n in [s*1024, (s+1)*1024).
//   g_dpart[s][b][m] = sum_n exp(Q[m].K[n])
// ---------------------------------------------------------------------------
__global__ __launch_bounds__(256) void denom_kernel()
{
    __shared__ __align__(16) uint8_t sm[4096];   // Q tile [128][8]h @0, K chunk @2048
    const uint32_t smb = smem_u32(sm);

    const int t = threadIdx.x, w = t >> 5, l = t & 31;
    const int b = blockIdx.z, s = blockIdx.y;
    const int mbase = blockIdx.x * 128;

    const uint4* Qg = (const uint4*)(g_Qh + (size_t)b * HW * CQD);
    const uint4* Kg = (const uint4*)(g_Kh + (size_t)b * HW * CQD);

    if (t < 128) *(uint4*)(sm + t * 16) = Qg[mbase + t];
    __syncthreads();
    uint32_t qa[2];
    ldsm2(qa, smb + (16 * w + (l & 15)) * 16);

    float rs0 = 0.0f, rs1 = 0.0f;
    for (int ch = 0; ch < (HW / NSPL) / 128; ch++) {
        const int nn0 = s * (HW / NSPL) + ch * 128;
        __syncthreads();
        if (t < 128) *(uint4*)(sm + 2048 + t * 16) = Kg[nn0 + t];
        __syncthreads();
        uint32_t kb[16];
        ldsm4(kb + 0,  smb + 2048 + l * 16);
        ldsm4(kb + 4,  smb + 2048 + (32 + l) * 16);
        ldsm4(kb + 8,  smb + 2048 + (64 + l) * 16);
        ldsm4(kb + 12, smb + 2048 + (96 + l) * 16);
#pragma unroll
        for (int j = 0; j < 16; j++) {
            float d0 = 0, d1 = 0, d2 = 0, d3 = 0;
            mma8(d0, d1, d2, d3, qa, kb[j]);
            rs0 += __expf(d0) + __expf(d1);
            rs1 += __expf(d2) + __expf(d3);
        }
    }
    rs0 += __shfl_xor_sync(0xFFFFFFFFu, rs0, 1);
    rs0 += __shfl_xor_sync(0xFFFFFFFFu, rs0, 2);
    rs1 += __shfl_xor_sync(0xFFFFFFFFu, rs1, 1);
    rs1 += __shfl_xor_sync(0xFFFFFFFFu, rs1, 2);
    if ((l & 3) == 0) {
        const int r = 16 * w + (l >> 2);
        float* dst = g_dpart + ((size_t)s * NBAT + b) * HW + mbase;
        dst[r]     = rs0;
        dst[r + 8] = rs1;
    }
}

// ---------------------------------------------------------------------------
// Kernel 3: prescale V in place:  V[c][m] *= 4096/denom[m]
// ---------------------------------------------------------------------------
__global__ __launch_bounds__(256) void vscale_kernel()
{
    const int t = threadIdx.x;
    const int b = blockIdx.y;
    const int m = blockIdx.x * 256 + t;
    float d = g_dpart[(size_t)b * HW + m]
            + g_dpart[((size_t)NBAT + b) * HW + m]
            + g_dpart[((size_t)2 * NBAT + b) * HW + m]
            + g_dpart[((size_t)3 * NBAT + b) * HW + m];
    const float inv = __fdividef(4096.0f, d);
    __half* Vp = g_Vh + (size_t)b * CCH * HW + m;
#pragma unroll
    for (int c = 0; c < CCH; c++)
        Vp[(size_t)c * HW] = __float2half(__half2float(Vp[(size_t)c * HW]) * inv);
}

// ---------------------------------------------------------------------------
// Kernel 4: attention aggregation, fully tensor-core.
//   Per block: 128 pixels (n), 8 warps (16 rows each).
//   Per 128-m chunk: S = K(A) x Q(B) via mma8 -> exp in regs -> f16 A-frags
//   -> D += P x V'(B via ldmatrix) via mma16.  P never touches smem.
// SMEM: V [64][272B] @0 (17408) | K [128][16B] @17408 | Q @19456
//       epilogue staging f32 [128][65] overlaps everything (33280 B)
// ---------------------------------------------------------------------------
#define VSTR  272
#define SM_V  0
#define SM_K  17408
#define SM_Q  19456
#define SMA_BYTES 33280
#define OSTR  65

__global__ __launch_bounds__(256) void attn_kernel(
    const float* __restrict__ x,
    const float* __restrict__ gamma,
    float* __restrict__ out)
{
    __shared__ __align__(16) uint8_t sm[SMA_BYTES];
    const uint32_t smb = smem_u32(sm);

    const int t = threadIdx.x, w = t >> 5, l = t & 31;
    const int b = blockIdx.y;
    const int n0 = blockIdx.x * 128;

    const uint4* Kg = (const uint4*)(g_Kh + (size_t)b * HW * CQD);
    const uint4* Qg = (const uint4*)(g_Qh + (size_t)b * HW * CQD);
    const uint4* Vg = (const uint4*)(g_Vh + (size_t)b * CCH * HW);

    // K tile [128][8]h staged once; warp's A-frag (rows 16w..16w+15)
    if (t < 128) *(uint4*)(sm + SM_K + t * 16) = Kg[n0 + t];
    __syncthreads();
    uint32_t ka[2];
    ldsm2(ka, smb + SM_K + (16 * w + (l & 15)) * 16);

    float dacc[8][4];
#pragma unroll
    for (int ct = 0; ct < 8; ct++)
#pragma unroll
        for (int i = 0; i < 4; i++) dacc[ct][i] = 0.0f;

    for (int chunk = 0; chunk < HW / 128; chunk++) {
        const int m0 = chunk * 128;
        __syncthreads();
        if (t < 128) *(uint4*)(sm + SM_Q + t * 16) = Qg[m0 + t];
#pragma unroll
        for (int jj = 0; jj < 4; jj++) {
            int i = t + jj * 256;              // 0..1023
            int row = i >> 4, c16 = i & 15;
            uint4 v = Vg[(size_t)row * (HW / 8) + (m0 >> 3) + c16];
            *(uint4*)(sm + SM_V + row * VSTR + c16 * 16) = v;
        }
        __syncthreads();

        // ---- scores -> P A-frags (registers only) ----
        uint32_t pa[8][4];
#pragma unroll
        for (int half = 0; half < 2; half++) {
            uint32_t qb[8];
            ldsm4(qb + 0, smb + SM_Q + (64 * half + l) * 16);
            ldsm4(qb + 4, smb + SM_Q + (64 * half + 32 + l) * 16);
#pragma unroll
            for (int j = 0; j < 8; j++) {
                float d0 = 0, d1 = 0, d2 = 0, d3 = 0;
                mma8(d0, d1, d2, d3, ka, qb[j]);
                const int jt = 8 * half + j;
                pa[jt >> 1][(jt & 1) * 2]     = cvt_h2(__expf(d0), __expf(d1));
                pa[jt >> 1][(jt & 1) * 2 + 1] = cvt_h2(__expf(d2), __expf(d3));
            }
        }

        // ---- D += P @ V' ----
#pragma unroll
        for (int kk = 0; kk < 8; kk++) {
#pragma unroll
            for (int ct = 0; ct < 8; ct++) {
                uint32_t bb[2];
                ldsm2(bb, smb + SM_V + (ct * 8 + (l & 7)) * VSTR
                          + kk * 32 + (((l & 15) >> 3) * 16));
                mma16(dacc[ct], pa[kk], bb[0], bb[1]);
            }
        }
    }

    // ---- epilogue: stage D through smem for coalesced writes ----
    __syncthreads();
    float* sD = (float*)sm;
    const int r = l >> 2, q = l & 3;
#pragma unroll
    for (int ct = 0; ct < 8; ct++) {
        const int c = ct * 8 + 2 * q;
        sD[(16 * w + r) * OSTR + c]         = dacc[ct][0];
        sD[(16 * w + r) * OSTR + c + 1]     = dacc[ct][1];
        sD[(16 * w + r + 8) * OSTR + c]     = dacc[ct][2];
        sD[(16 * w + r + 8) * OSTR + c + 1] = dacc[ct][3];
    }
    __syncthreads();

    const float gm = gamma[0] * (1.0f / 4096.0f);   // undo vscale's x4096
#pragma unroll
    for (int i = t; i < 128 * CCH; i += 256) {
        const int c = i >> 7, n = i & 127;
        const size_t gi = (size_t)b * CCH * HW + (size_t)c * HW + n0 + n;
        out[gi] = gm * sD[n * OSTR + c] + x[gi];
    }
}

// ---------------------------------------------------------------------------
extern "C" void kernel_launch(void* const* d_in, const int* in_sizes, int n_in,
                              void* d_out, int out_size)
{
    const float* x     = (const float*)d_in[0];
    const float* Wq    = (const float*)d_in[1];
    const float* bq    = (const float*)d_in[2];
    const float* Wk    = (const float*)d_in[3];
    const float* bk    = (const float*)d_in[4];
    const float* Wv    = (const float*)d_in[5];
    const float* bv    = (const float*)d_in[6];
    const float* gamma = (const float*)d_in[7];
    float* out = (float*)d_out;

    qkv_kernel<<<dim3(HW / 128, NBAT), 512>>>(x, Wq, bq, Wk, bk, Wv, bv);
    denom_kernel<<<dim3(HW / 128, NSPL, NBAT), 256>>>();
    vscale_kernel<<<dim3(HW / 256, NBAT), 256>>>();
    attn_kernel<<<dim3(HW / 128, NBAT), 256>>>(x, gamma, out);
}

// round 6
// speedup vs baseline: 7.7236x; 1.0990x over previous
#include <cuda_runtime.h>
#include <cuda_fp16.h>
#include <cstdint>

// Problem constants
#define HW   4096
#define CCH  64
#define CQD  8
#define NBAT 4
#define NSPL 4          // denom j-split (deterministic partials, no atomics)
#define NS   4          // attn key-split
#define PSZ  (NBAT * CCH * HW)

// Scratch (device globals — no allocation allowed)
__device__ __half g_Qh[NBAT * HW * CQD];      // [b][m][8] fp16
__device__ __half g_Kh[NBAT * HW * CQD];      // [b][n][8] fp16
__device__ __half g_Vh[NBAT * CCH * HW];      // [b][c][m] fp16 (vscale: *= 4096/denom[m])
__device__ float  g_dpart[NSPL * NBAT * HW];  // per-split softmax denominators
__device__ float  g_Dp[NS * PSZ];             // attn split partials [s][b][c][n]

// ---------------------------------------------------------------------------
// helpers
// ---------------------------------------------------------------------------
__device__ __forceinline__ unsigned long long pack2(float lo, float hi) {
    unsigned long long r;
    asm("mov.b64 %0, {%1, %2};" : "=l"(r) : "f"(lo), "f"(hi));
    return r;
}
__device__ __forceinline__ void unpack2(unsigned long long v, float& lo, float& hi) {
    asm("mov.b64 {%0, %1}, %2;" : "=f"(lo), "=f"(hi) : "l"(v));
}
__device__ __forceinline__ unsigned long long fma2(unsigned long long a,
                                                   unsigned long long b,
                                                   unsigned long long c) {
    unsigned long long d;
    asm("fma.rn.f32x2 %0, %1, %2, %3;" : "=l"(d) : "l"(a), "l"(b), "l"(c));
    return d;
}
__device__ __forceinline__ uint32_t smem_u32(const void* p) {
    uint32_t a;
    asm("{ .reg .u64 t; cvta.to.shared.u64 t, %1; cvt.u32.u64 %0, t; }" : "=r"(a) : "l"(p));
    return a;
}
__device__ __forceinline__ void ldsm2(uint32_t* r, uint32_t addr) {
    asm volatile("ldmatrix.sync.aligned.m8n8.x2.shared.b16 {%0,%1}, [%2];"
                 : "=r"(r[0]), "=r"(r[1]) : "r"(addr));
}
__device__ __forceinline__ void ldsm4(uint32_t* r, uint32_t addr) {
    asm volatile("ldmatrix.sync.aligned.m8n8.x4.shared.b16 {%0,%1,%2,%3}, [%4];"
                 : "=r"(r[0]), "=r"(r[1]), "=r"(r[2]), "=r"(r[3]) : "r"(addr));
}
// S-tile: D(16x8) = A(16x8) x B(8x8), fp16 in, fp32 acc
__device__ __forceinline__ void mma8(float& d0, float& d1, float& d2, float& d3,
                                     const uint32_t* a, uint32_t b) {
    asm volatile("mma.sync.aligned.m16n8k8.row.col.f32.f16.f16.f32 "
                 "{%0,%1,%2,%3}, {%4,%5}, {%6}, {%0,%1,%2,%3};"
                 : "+f"(d0), "+f"(d1), "+f"(d2), "+f"(d3)
                 : "r"(a[0]), "r"(a[1]), "r"(b));
}
// P@V: D(16x8) += A(16x16) x B(16x8)
__device__ __forceinline__ void mma16(float* d, const uint32_t* a,
                                      uint32_t b0, uint32_t b1) {
    asm volatile("mma.sync.aligned.m16n8k16.row.col.f32.f16.f16.f32 "
                 "{%0,%1,%2,%3}, {%4,%5,%6,%7}, {%8,%9}, {%0,%1,%2,%3};"
                 : "+f"(d[0]), "+f"(d[1]), "+f"(d[2]), "+f"(d[3])
                 : "r"(a[0]), "r"(a[1]), "r"(a[2]), "r"(a[3]), "r"(b0), "r"(b1));
}
__device__ __forceinline__ uint32_t cvt_h2(float lo, float hi) {
    uint32_t r;
    asm("cvt.rn.f16x2.f32 %0, %1, %2;" : "=r"(r) : "f"(hi), "f"(lo));
    return r;
}

// ---------------------------------------------------------------------------
// Kernel 1: QKV projections.  4 threads per pixel (h = channel group).
// ---------------------------------------------------------------------------
__global__ __launch_bounds__(512) void qkv_kernel(
    const float* __restrict__ x,
    const float* __restrict__ Wq, const float* __restrict__ bq,
    const float* __restrict__ Wk, const float* __restrict__ bk,
    const float* __restrict__ Wv, const float* __restrict__ bv)
{
    __shared__ float WqT[CCH][CQD];
    __shared__ float WkT[CCH][CQD];
    __shared__ float WvT[CCH][CCH];

    const int t = threadIdx.x;
    for (int i = t; i < CCH * CQD; i += 512) {
        int o = i / CCH, c = i % CCH;
        WqT[c][o] = Wq[i];
        WkT[c][o] = Wk[i];
    }
    for (int i = t; i < CCH * CCH; i += 512) {
        int o = i / CCH, c = i % CCH;
        WvT[c][o] = Wv[i];
    }
    __syncthreads();

    const int b  = blockIdx.y;
    const int px = t & 127;
    const int h  = t >> 7;             // warp-uniform channel group
    const int n  = blockIdx.x * 128 + px;
    const float* xp = x + (size_t)b * CCH * HW + n;

    unsigned long long va[8], qa[4], ka[4];
#pragma unroll
    for (int i = 0; i < 8; i++) va[i] = pack2(bv[16 * h + 2 * i], bv[16 * h + 2 * i + 1]);
    if (h == 0) {
#pragma unroll
        for (int i = 0; i < 4; i++) qa[i] = pack2(bq[2 * i], bq[2 * i + 1]);
    }
    if (h == 1) {
#pragma unroll
        for (int i = 0; i < 4; i++) ka[i] = pack2(bk[2 * i], bk[2 * i + 1]);
    }

#pragma unroll 4
    for (int c = 0; c < CCH; c++) {
        float xv = xp[(size_t)c * HW];
        unsigned long long xx = pack2(xv, xv);
        const unsigned long long* wv2 = (const unsigned long long*)&WvT[c][16 * h];
#pragma unroll
        for (int i = 0; i < 8; i++) va[i] = fma2(xx, wv2[i], va[i]);
        if (h == 0) {
            const unsigned long long* wq2 = (const unsigned long long*)WqT[c];
#pragma unroll
            for (int i = 0; i < 4; i++) qa[i] = fma2(xx, wq2[i], qa[i]);
        }
        if (h == 1) {
            const unsigned long long* wk2 = (const unsigned long long*)WkT[c];
#pragma unroll
            for (int i = 0; i < 4; i++) ka[i] = fma2(xx, wk2[i], ka[i]);
        }
    }

    __half* Vp = g_Vh + ((size_t)b * CCH + 16 * h) * HW + n;
#pragma unroll
    for (int i = 0; i < 8; i++) {
        float lo, hi;
        unpack2(va[i], lo, hi);
        Vp[(size_t)(2 * i) * HW]     = __float2half(lo);
        Vp[(size_t)(2 * i + 1) * HW] = __float2half(hi);
    }
    if (h == 0) {
        uint32_t u[4];
#pragma unroll
        for (int i = 0; i < 4; i++) {
            float lo, hi;
            unpack2(qa[i], lo, hi);
            u[i] = cvt_h2(lo, hi);
        }
        *(uint4*)(g_Qh + ((size_t)b * HW + n) * CQD) = make_uint4(u[0], u[1], u[2], u[3]);
    }
    if (h == 1) {
        uint32_t u[4];
#pragma unroll
        for (int i = 0; i < 4; i++) {
            float lo, hi;
            unpack2(ka[i], lo, hi);
            u[i] = cvt_h2(lo, hi);
        }
        *(uint4*)(g_Kh + ((size_t)b * HW + n) * CQD) = make_uint4(u[0], u[1], u[2], u[3]);
    }
}

// ---------------------------------------------------------------------------
// Kernel 2: softmax denominators via MMA scores.
// ---------------------------------------------------------------------------
__global__ __launch_bounds__(256) void denom_kernel()
{
    __shared__ __align__(16) uint8_t sm[4096];   // Q tile [128][8]h @0, K chunk @2048
    const uint32_t smb = smem_u32(sm);

    const int t = threadIdx.x, w = t >> 5, l = t & 31;
    const int b = blockIdx.z, s = blockIdx.y;
    const int mbase = blockIdx.x * 128;

    const uint4* Qg = (const uint4*)(g_Qh + (size_t)b * HW * CQD);
    const uint4* Kg = (const uint4*)(g_Kh + (size_t)b * HW * CQD);

    if (t < 128) *(uint4*)(sm + t * 16) = Qg[mbase + t];
    __syncthreads();
    uint32_t qa[2];
    ldsm2(qa, smb + (16 * w + (l & 15)) * 16);

    float rs0 = 0.0f, rs1 = 0.0f;
    for (int ch = 0; ch < (HW / NSPL) / 128; ch++) {
        const int nn0 = s * (HW / NSPL) + ch * 128;
        __syncthreads();
        if (t < 128) *(uint4*)(sm + 2048 + t * 16) = Kg[nn0 + t];
        __syncthreads();
        uint32_t kb[16];
        ldsm4(kb + 0,  smb + 2048 + l * 16);
        ldsm4(kb + 4,  smb + 2048 + (32 + l) * 16);
        ldsm4(kb + 8,  smb + 2048 + (64 + l) * 16);
        ldsm4(kb + 12, smb + 2048 + (96 + l) * 16);
#pragma unroll
        for (int j = 0; j < 16; j++) {
            float d0 = 0, d1 = 0, d2 = 0, d3 = 0;
            mma8(d0, d1, d2, d3, qa, kb[j]);
            rs0 += __expf(d0) + __expf(d1);
            rs1 += __expf(d2) + __expf(d3);
        }
    }
    rs0 += __shfl_xor_sync(0xFFFFFFFFu, rs0, 1);
    rs0 += __shfl_xor_sync(0xFFFFFFFFu, rs0, 2);
    rs1 += __shfl_xor_sync(0xFFFFFFFFu, rs1, 1);
    rs1 += __shfl_xor_sync(0xFFFFFFFFu, rs1, 2);
    if ((l & 3) == 0) {
        const int r = 16 * w + (l >> 2);
        float* dst = g_dpart + ((size_t)s * NBAT + b) * HW + mbase;
        dst[r]     = rs0;
        dst[r + 8] = rs1;
    }
}

// ---------------------------------------------------------------------------
// Kernel 3: prescale V in place:  V[c][m] *= 4096/denom[m]
// ---------------------------------------------------------------------------
__global__ __launch_bounds__(256) void vscale_kernel()
{
    const int t = threadIdx.x;
    const int b = blockIdx.y;
    const int m = blockIdx.x * 256 + t;
    float d = g_dpart[(size_t)b * HW + m]
            + g_dpart[((size_t)NBAT + b) * HW + m]
            + g_dpart[((size_t)2 * NBAT + b) * HW + m]
            + g_dpart[((size_t)3 * NBAT + b) * HW + m];
    const float inv = __fdividef(4096.0f, d);
    __half* Vp = g_Vh + (size_t)b * CCH * HW + m;
#pragma unroll
    for (int c = 0; c < CCH; c++)
        Vp[(size_t)c * HW] = __float2half(__half2float(Vp[(size_t)c * HW]) * inv);
}

// ---------------------------------------------------------------------------
// Kernel 4: attention aggregation, split over keys (NS splits).
//   Block (x=n-tile, y=split s, z=b): 128 pixels, keys [s*1024,(s+1)*1024).
//   Scores via mma8 (regs) -> exp -> f16 A-frags -> D += P@V' via mma16.
//   Partial D written [s][b][c][n] (coalesced via smem transpose).
// ---------------------------------------------------------------------------
#define VSTR  272
#define SM_V  0
#define SM_K  17408
#define SM_Q  19456
#define SMA_BYTES 33280
#define OSTR  65

__global__ __launch_bounds__(256, 3) void attn_kernel()
{
    __shared__ __align__(16) uint8_t sm[SMA_BYTES];
    const uint32_t smb = smem_u32(sm);

    const int t = threadIdx.x, w = t >> 5, l = t & 31;
    const int s = blockIdx.y;
    const int b = blockIdx.z;
    const int n0 = blockIdx.x * 128;

    const uint4* Kg = (const uint4*)(g_Kh + (size_t)b * HW * CQD);
    const uint4* Qg = (const uint4*)(g_Qh + (size_t)b * HW * CQD);
    const uint4* Vg = (const uint4*)(g_Vh + (size_t)b * CCH * HW);

    if (t < 128) *(uint4*)(sm + SM_K + t * 16) = Kg[n0 + t];
    __syncthreads();
    uint32_t ka[2];
    ldsm2(ka, smb + SM_K + (16 * w + (l & 15)) * 16);

    float dacc[8][4];
#pragma unroll
    for (int ct = 0; ct < 8; ct++)
#pragma unroll
        for (int i = 0; i < 4; i++) dacc[ct][i] = 0.0f;

    for (int chunk = 0; chunk < HW / (NS * 128); chunk++) {
        const int m0 = (s * (HW / (NS * 128)) + chunk) * 128;
        __syncthreads();
        if (t < 128) *(uint4*)(sm + SM_Q + t * 16) = Qg[m0 + t];
#pragma unroll
        for (int jj = 0; jj < 4; jj++) {
            int i = t + jj * 256;              // 0..1023
            int row = i >> 4, c16 = i & 15;
            uint4 v = Vg[(size_t)row * (HW / 8) + (m0 >> 3) + c16];
            *(uint4*)(sm + SM_V + row * VSTR + c16 * 16) = v;
        }
        __syncthreads();

        // ---- scores -> P A-frags (registers only) ----
        uint32_t pa[8][4];
#pragma unroll
        for (int half = 0; half < 2; half++) {
            uint32_t qb[8];
            ldsm4(qb + 0, smb + SM_Q + (64 * half + l) * 16);
            ldsm4(qb + 4, smb + SM_Q + (64 * half + 32 + l) * 16);
#pragma unroll
            for (int j = 0; j < 8; j++) {
                float d0 = 0, d1 = 0, d2 = 0, d3 = 0;
                mma8(d0, d1, d2, d3, ka, qb[j]);
                const int jt = 8 * half + j;
                pa[jt >> 1][(jt & 1) * 2]     = cvt_h2(__expf(d0), __expf(d1));
                pa[jt >> 1][(jt & 1) * 2 + 1] = cvt_h2(__expf(d2), __expf(d3));
            }
        }

        // ---- D += P @ V' (ldsm4 feeds two channel tiles at once) ----
#pragma unroll
        for (int kk = 0; kk < 8; kk++) {
#pragma unroll
            for (int cp = 0; cp < 4; cp++) {
                uint32_t bb[4];
                ldsm4(bb, smb + SM_V
                          + (cp * 16 + ((l >> 4) << 3) + (l & 7)) * VSTR
                          + kk * 32 + ((l >> 3) & 1) * 16);
                mma16(dacc[2 * cp],     pa[kk], bb[0], bb[1]);
                mma16(dacc[2 * cp + 1], pa[kk], bb[2], bb[3]);
            }
        }
    }

    // ---- stage partial D through smem, write [s][b][c][n] coalesced ----
    __syncthreads();
    float* sD = (float*)sm;
    const int r = l >> 2, q = l & 3;
#pragma unroll
    for (int ct = 0; ct < 8; ct++) {
        const int c = ct * 8 + 2 * q;
        sD[(16 * w + r) * OSTR + c]         = dacc[ct][0];
        sD[(16 * w + r) * OSTR + c + 1]     = dacc[ct][1];
        sD[(16 * w + r + 8) * OSTR + c]     = dacc[ct][2];
        sD[(16 * w + r + 8) * OSTR + c + 1] = dacc[ct][3];
    }
    __syncthreads();

    float* dst = g_Dp + (size_t)s * PSZ + (size_t)b * CCH * HW;
#pragma unroll
    for (int i = t; i < 128 * CCH; i += 256) {
        const int c = i >> 7, n = i & 127;
        dst[(size_t)c * HW + n0 + n] = sD[n * OSTR + c];
    }
}

// ---------------------------------------------------------------------------
// Kernel 5: combine split partials + gamma + residual (vectorized)
// ---------------------------------------------------------------------------
__global__ __launch_bounds__(256) void combine_kernel(
    const float* __restrict__ x,
    const float* __restrict__ gamma,
    float* __restrict__ out)
{
    const size_t i = ((size_t)blockIdx.x * 256 + threadIdx.x) * 4;
    const float gm = gamma[0] * (1.0f / 4096.0f);
    float4 a = *(const float4*)(g_Dp + i);
    float4 c = *(const float4*)(g_Dp + PSZ + i);
    float4 d = *(const float4*)(g_Dp + 2 * (size_t)PSZ + i);
    float4 e = *(const float4*)(g_Dp + 3 * (size_t)PSZ + i);
    float4 xv = *(const float4*)(x + i);
    float4 o;
    o.x = gm * ((a.x + c.x) + (d.x + e.x)) + xv.x;
    o.y = gm * ((a.y + c.y) + (d.y + e.y)) + xv.y;
    o.z = gm * ((a.z + c.z) + (d.z + e.z)) + xv.z;
    o.w = gm * ((a.w + c.w) + (d.w + e.w)) + xv.w;
    *(float4*)(out + i) = o;
}

// ---------------------------------------------------------------------------
extern "C" void kernel_launch(void* const* d_in, const int* in_sizes, int n_in,
                              void* d_out, int out_size)
{
    const float* x     = (const float*)d_in[0];
    const float* Wq    = (const float*)d_in[1];
    const float* bq    = (const float*)d_in[2];
    const float* Wk    = (const float*)d_in[3];
    const float* bk    = (const float*)d_in[4];
    const float* Wv    = (const float*)d_in[5];
    const float* bv    = (const float*)d_in[6];
    const float* gamma = (const float*)d_in[7];
    float* out = (float*)d_out;

    qkv_kernel<<<dim3(HW / 128, NBAT), 512>>>(x, Wq, bq, Wk, bk, Wv, bv);
    denom_kernel<<<dim3(HW / 128, NSPL, NBAT), 256>>>();
    vscale_kernel<<<dim3(HW / 256, NBAT), 256>>>();
    attn_kernel<<<dim3(HW / 128, NS, NBAT), 256>>>();
    combine_kernel<<<PSZ / 1024, 256>>>(x, gamma, out);
}

// round 7
// speedup vs baseline: 8.9660x; 1.1608x over previous
#include <cuda_runtime.h>
#include <cuda_fp16.h>
#include <cstdint>

// Problem constants
#define HW   4096
#define CCH  64
#define CQD  8
#define NBAT 4
#define NSPL 4          // denom j-split
#define NS   4          // attn key-split
#define PSZ  (NBAT * CCH * HW)
#define L2E  1.4426950408889634f

// Scratch (device globals — no allocation allowed)
__device__ __half g_Qh[NBAT * HW * CQD];      // [b][m][8] fp16, pre-scaled by log2(e)
__device__ __half g_Kh[NBAT * HW * CQD];      // [b][n][8] fp16
__device__ __half g_Vh[NBAT * CCH * HW];      // [b][c][m] fp16 (vscale: *= 4096/denom[m])
__device__ float  g_dpart[NSPL * NBAT * HW];  // per-split softmax denominators
__device__ float  g_Dp[NS * PSZ];             // attn split partials [s][b][c][n]

// ---------------------------------------------------------------------------
// helpers
// ---------------------------------------------------------------------------
__device__ __forceinline__ unsigned long long pack2(float lo, float hi) {
    unsigned long long r;
    asm("mov.b64 %0, {%1, %2};" : "=l"(r) : "f"(lo), "f"(hi));
    return r;
}
__device__ __forceinline__ void unpack2(unsigned long long v, float& lo, float& hi) {
    asm("mov.b64 {%0, %1}, %2;" : "=f"(lo), "=f"(hi) : "l"(v));
}
__device__ __forceinline__ unsigned long long fma2(unsigned long long a,
                                                   unsigned long long b,
                                                   unsigned long long c) {
    unsigned long long d;
    asm("fma.rn.f32x2 %0, %1, %2, %3;" : "=l"(d) : "l"(a), "l"(b), "l"(c));
    return d;
}
__device__ __forceinline__ uint32_t smem_u32(const void* p) {
    uint32_t a;
    asm("{ .reg .u64 t; cvta.to.shared.u64 t, %1; cvt.u32.u64 %0, t; }" : "=r"(a) : "l"(p));
    return a;
}
__device__ __forceinline__ void ldsm2(uint32_t* r, uint32_t addr) {
    asm volatile("ldmatrix.sync.aligned.m8n8.x2.shared.b16 {%0,%1}, [%2];"
                 : "=r"(r[0]), "=r"(r[1]) : "r"(addr));
}
__device__ __forceinline__ void ldsm4(uint32_t* r, uint32_t addr) {
    asm volatile("ldmatrix.sync.aligned.m8n8.x4.shared.b16 {%0,%1,%2,%3}, [%4];"
                 : "=r"(r[0]), "=r"(r[1]), "=r"(r[2]), "=r"(r[3]) : "r"(addr));
}
__device__ __forceinline__ void mma8(float& d0, float& d1, float& d2, float& d3,
                                     const uint32_t* a, uint32_t b) {
    asm volatile("mma.sync.aligned.m16n8k8.row.col.f32.f16.f16.f32 "
                 "{%0,%1,%2,%3}, {%4,%5}, {%6}, {%0,%1,%2,%3};"
                 : "+f"(d0), "+f"(d1), "+f"(d2), "+f"(d3)
                 : "r"(a[0]), "r"(a[1]), "r"(b));
}
__device__ __forceinline__ void mma16(float* d, const uint32_t* a,
                                      uint32_t b0, uint32_t b1) {
    asm volatile("mma.sync.aligned.m16n8k16.row.col.f32.f16.f16.f32 "
                 "{%0,%1,%2,%3}, {%4,%5,%6,%7}, {%8,%9}, {%0,%1,%2,%3};"
                 : "+f"(d[0]), "+f"(d[1]), "+f"(d[2]), "+f"(d[3])
                 : "r"(a[0]), "r"(a[1]), "r"(a[2]), "r"(a[3]), "r"(b0), "r"(b1));
}
__device__ __forceinline__ uint32_t cvt_h2(float lo, float hi) {
    uint32_t r;
    asm("cvt.rn.f16x2.f32 %0, %1, %2;" : "=r"(r) : "f"(hi), "f"(lo));
    return r;
}
__device__ __forceinline__ uint32_t h2ex2(uint32_t a) {   // 2^x on both halves
    uint32_t r;
    asm("ex2.approx.f16x2 %0, %1;" : "=r"(r) : "r"(a));
    return r;
}
__device__ __forceinline__ uint32_t hadd2_(uint32_t a, uint32_t b) {
    uint32_t r;
    asm("add.f16x2 %0, %1, %2;" : "=r"(r) : "r"(a), "r"(b));
    return r;
}
__device__ __forceinline__ void cp16(uint32_t smem, const void* g) {
    asm volatile("cp.async.cg.shared.global [%0], [%1], 16;" :: "r"(smem), "l"(g));
}
#define CP_COMMIT() asm volatile("cp.async.commit_group;" ::: "memory")
#define CP_WAIT(n)  asm volatile("cp.async.wait_group %0;" :: "n"(n) : "memory")

// ---------------------------------------------------------------------------
// Kernel 1: QKV projections.  4 threads per pixel (h = channel group).
//   Q is stored pre-scaled by log2(e) so scores land in log2 domain.
// ---------------------------------------------------------------------------
__global__ __launch_bounds__(512) void qkv_kernel(
    const float* __restrict__ x,
    const float* __restrict__ Wq, const float* __restrict__ bq,
    const float* __restrict__ Wk, const float* __restrict__ bk,
    const float* __restrict__ Wv, const float* __restrict__ bv)
{
    __shared__ float WqT[CCH][CQD];
    __shared__ float WkT[CCH][CQD];
    __shared__ float WvT[CCH][CCH];

    const int t = threadIdx.x;
    for (int i = t; i < CCH * CQD; i += 512) {
        int o = i / CCH, c = i % CCH;
        WqT[c][o] = Wq[i] * L2E;           // fold log2(e) into Q
        WkT[c][o] = Wk[i];
    }
    for (int i = t; i < CCH * CCH; i += 512) {
        int o = i / CCH, c = i % CCH;
        WvT[c][o] = Wv[i];
    }
    __syncthreads();

    const int b  = blockIdx.y;
    const int px = t & 127;
    const int h  = t >> 7;
    const int n  = blockIdx.x * 128 + px;
    const float* xp = x + (size_t)b * CCH * HW + n;

    unsigned long long va[8], qa[4], ka[4];
#pragma unroll
    for (int i = 0; i < 8; i++) va[i] = pack2(bv[16 * h + 2 * i], bv[16 * h + 2 * i + 1]);
    if (h == 0) {
#pragma unroll
        for (int i = 0; i < 4; i++) qa[i] = pack2(bq[2 * i] * L2E, bq[2 * i + 1] * L2E);
    }
    if (h == 1) {
#pragma unroll
        for (int i = 0; i < 4; i++) ka[i] = pack2(bk[2 * i], bk[2 * i + 1]);
    }

#pragma unroll 4
    for (int c = 0; c < CCH; c++) {
        float xv = xp[(size_t)c * HW];
        unsigned long long xx = pack2(xv, xv);
        const unsigned long long* wv2 = (const unsigned long long*)&WvT[c][16 * h];
#pragma unroll
        for (int i = 0; i < 8; i++) va[i] = fma2(xx, wv2[i], va[i]);
        if (h == 0) {
            const unsigned long long* wq2 = (const unsigned long long*)WqT[c];
#pragma unroll
            for (int i = 0; i < 4; i++) qa[i] = fma2(xx, wq2[i], qa[i]);
        }
        if (h == 1) {
            const unsigned long long* wk2 = (const unsigned long long*)WkT[c];
#pragma unroll
            for (int i = 0; i < 4; i++) ka[i] = fma2(xx, wk2[i], ka[i]);
        }
    }

    __half* Vp = g_Vh + ((size_t)b * CCH + 16 * h) * HW + n;
#pragma unroll
    for (int i = 0; i < 8; i++) {
        float lo, hi;
        unpack2(va[i], lo, hi);
        Vp[(size_t)(2 * i) * HW]     = __float2half(lo);
        Vp[(size_t)(2 * i + 1) * HW] = __float2half(hi);
    }
    if (h == 0) {
        uint32_t u[4];
#pragma unroll
        for (int i = 0; i < 4; i++) {
            float lo, hi;
            unpack2(qa[i], lo, hi);
            u[i] = cvt_h2(lo, hi);
        }
        *(uint4*)(g_Qh + ((size_t)b * HW + n) * CQD) = make_uint4(u[0], u[1], u[2], u[3]);
    }
    if (h == 1) {
        uint32_t u[4];
#pragma unroll
        for (int i = 0; i < 4; i++) {
            float lo, hi;
            unpack2(ka[i], lo, hi);
            u[i] = cvt_h2(lo, hi);
        }
        *(uint4*)(g_Kh + ((size_t)b * HW + n) * CQD) = make_uint4(u[0], u[1], u[2], u[3]);
    }
}

// ---------------------------------------------------------------------------
// Kernel 2: softmax denominators via MMA scores + f16x2 ex2.
// ---------------------------------------------------------------------------
__global__ __launch_bounds__(256) void denom_kernel()
{
    __shared__ __align__(16) uint8_t sm[4096];   // Q tile @0, K chunk @2048
    const uint32_t smb = smem_u32(sm);

    const int t = threadIdx.x, w = t >> 5, l = t & 31;
    const int b = blockIdx.z, s = blockIdx.y;
    const int mbase = blockIdx.x * 128;

    const uint4* Qg = (const uint4*)(g_Qh + (size_t)b * HW * CQD);
    const uint4* Kg = (const uint4*)(g_Kh + (size_t)b * HW * CQD);

    if (t < 128) *(uint4*)(sm + t * 16) = Qg[mbase + t];
    __syncthreads();
    uint32_t qa[2];
    ldsm2(qa, smb + (16 * w + (l & 15)) * 16);

    float rs0 = 0.0f, rs1 = 0.0f;
    for (int ch = 0; ch < (HW / NSPL) / 128; ch++) {
        const int nn0 = s * (HW / NSPL) + ch * 128;
        __syncthreads();
        if (t < 128) *(uint4*)(sm + 2048 + t * 16) = Kg[nn0 + t];
        __syncthreads();
        uint32_t kb[16];
        ldsm4(kb + 0,  smb + 2048 + l * 16);
        ldsm4(kb + 4,  smb + 2048 + (32 + l) * 16);
        ldsm4(kb + 8,  smb + 2048 + (64 + l) * 16);
        ldsm4(kb + 12, smb + 2048 + (96 + l) * 16);
        uint32_t a0 = 0u, a1 = 0u;     // per-chunk f16x2 accumulators
#pragma unroll
        for (int j = 0; j < 16; j++) {
            float d0 = 0, d1 = 0, d2 = 0, d3 = 0;
            mma8(d0, d1, d2, d3, qa, kb[j]);
            a0 = hadd2_(a0, h2ex2(cvt_h2(d0, d1)));
            a1 = hadd2_(a1, h2ex2(cvt_h2(d2, d3)));
        }
        float2 f0 = __half22float2(*reinterpret_cast<__half2*>(&a0));
        float2 f1 = __half22float2(*reinterpret_cast<__half2*>(&a1));
        rs0 += f0.x + f0.y;
        rs1 += f1.x + f1.y;
    }
    rs0 += __shfl_xor_sync(0xFFFFFFFFu, rs0, 1);
    rs0 += __shfl_xor_sync(0xFFFFFFFFu, rs0, 2);
    rs1 += __shfl_xor_sync(0xFFFFFFFFu, rs1, 1);
    rs1 += __shfl_xor_sync(0xFFFFFFFFu, rs1, 2);
    if ((l & 3) == 0) {
        const int r = 16 * w + (l >> 2);
        float* dst = g_dpart + ((size_t)s * NBAT + b) * HW + mbase;
        dst[r]     = rs0;
        dst[r + 8] = rs1;
    }
}

// ---------------------------------------------------------------------------
// Kernel 3: prescale V in place:  V[c][m] *= 4096/denom[m]
// ---------------------------------------------------------------------------
__global__ __launch_bounds__(256) void vscale_kernel()
{
    const int t = threadIdx.x;
    const int b = blockIdx.y;
    const int m = blockIdx.x * 256 + t;
    float d = g_dpart[(size_t)b * HW + m]
            + g_dpart[((size_t)NBAT + b) * HW + m]
            + g_dpart[((size_t)2 * NBAT + b) * HW + m]
            + g_dpart[((size_t)3 * NBAT + b) * HW + m];
    const float inv = __fdividef(4096.0f, d);
    __half* Vp = g_Vh + (size_t)b * CCH * HW + m;
#pragma unroll
    for (int c = 0; c < CCH; c++)
        Vp[(size_t)c * HW] = __float2half(__half2float(Vp[(size_t)c * HW]) * inv);
}

// ---------------------------------------------------------------------------
// Kernel 4: attention aggregation, split over keys, cp.async double-buffered.
// SMEM: V0 @0, V1 @17408 (each 64 x 272B) | Q0 @34816, Q1 @36864 | K @38912
//       epilogue staging f32 [128][65] overlaps V buffers
// ---------------------------------------------------------------------------
#define VSTR  272
#define SM_V0 0
#define SM_V1 17408
#define SM_Q0 34816
#define SM_Q1 36864
#define SM_K  38912
#define SMA_BYTES 40960
#define OSTR  65

__global__ __launch_bounds__(256, 3) void attn_kernel()
{
    __shared__ __align__(16) uint8_t sm[SMA_BYTES];
    const uint32_t smb = smem_u32(sm);

    const int t = threadIdx.x, w = t >> 5, l = t & 31;
    const int s = blockIdx.y;
    const int b = blockIdx.z;
    const int n0 = blockIdx.x * 128;
    const int NC = HW / (NS * 128);

    const uint4* Kg = (const uint4*)(g_Kh + (size_t)b * HW * CQD);
    const uint4* Qg = (const uint4*)(g_Qh + (size_t)b * HW * CQD);
    const uint4* Vg = (const uint4*)(g_Vh + (size_t)b * CCH * HW);

    if (t < 128) *(uint4*)(sm + SM_K + t * 16) = Kg[n0 + t];

    // async stage of chunk `c` into buffer `buf`
    auto stage = [&](int buf, int m0) {
        const uint32_t vbase = smb + (buf ? SM_V1 : SM_V0);
#pragma unroll
        for (int jj = 0; jj < 4; jj++) {
            int i = t + jj * 256;
            int row = i >> 4, c16 = i & 15;
            cp16(vbase + row * VSTR + c16 * 16,
                 Vg + (size_t)row * (HW / 8) + (m0 >> 3) + c16);
        }
        if (t < 128) cp16(smb + (buf ? SM_Q1 : SM_Q0) + t * 16, Qg + m0 + t);
    };

    stage(0, s * NC * 128);
    CP_COMMIT();

    __syncthreads();
    uint32_t ka[2];
    ldsm2(ka, smb + SM_K + (16 * w + (l & 15)) * 16);

    float dacc[8][4];
#pragma unroll
    for (int ct = 0; ct < 8; ct++)
#pragma unroll
        for (int i = 0; i < 4; i++) dacc[ct][i] = 0.0f;

    for (int chunk = 0; chunk < NC; chunk++) {
        const int buf = chunk & 1;
        if (chunk + 1 < NC) {
            stage(buf ^ 1, (s * NC + chunk + 1) * 128);
            CP_COMMIT();
            CP_WAIT(1);
        } else {
            CP_WAIT(0);
        }
        __syncthreads();

        const uint32_t vbase = smb + (buf ? SM_V1 : SM_V0);
        const uint32_t qbase = smb + (buf ? SM_Q1 : SM_Q0);

        // ---- scores -> P A-frags: mma8 -> cvt f16x2 -> ex2.f16x2 ----
        uint32_t pa[8][4];
#pragma unroll
        for (int half = 0; half < 2; half++) {
            uint32_t qb[8];
            ldsm4(qb + 0, qbase + (64 * half + l) * 16);
            ldsm4(qb + 4, qbase + (64 * half + 32 + l) * 16);
#pragma unroll
            for (int j = 0; j < 8; j++) {
                float d0 = 0, d1 = 0, d2 = 0, d3 = 0;
                mma8(d0, d1, d2, d3, ka, qb[j]);
                const int jt = 8 * half + j;
                pa[jt >> 1][(jt & 1) * 2]     = h2ex2(cvt_h2(d0, d1));
                pa[jt >> 1][(jt & 1) * 2 + 1] = h2ex2(cvt_h2(d2, d3));
            }
        }

        // ---- D += P @ V' ----
#pragma unroll
        for (int kk = 0; kk < 8; kk++) {
#pragma unroll
            for (int cp = 0; cp < 4; cp++) {
                uint32_t bb[4];
                ldsm4(bb, vbase
                          + (cp * 16 + ((l >> 4) << 3) + (l & 7)) * VSTR
                          + kk * 32 + ((l >> 3) & 1) * 16);
                mma16(dacc[2 * cp],     pa[kk], bb[0], bb[1]);
                mma16(dacc[2 * cp + 1], pa[kk], bb[2], bb[3]);
            }
        }
        __syncthreads();
    }

    // ---- stage partial D through smem, write [s][b][c][n] coalesced ----
    float* sD = (float*)sm;
    const int r = l >> 2, q = l & 3;
#pragma unroll
    for (int ct = 0; ct < 8; ct++) {
        const int c = ct * 8 + 2 * q;
        sD[(16 * w + r) * OSTR + c]         = dacc[ct][0];
        sD[(16 * w + r) * OSTR + c + 1]     = dacc[ct][1];
        sD[(16 * w + r + 8) * OSTR + c]     = dacc[ct][2];
        sD[(16 * w + r + 8) * OSTR + c + 1] = dacc[ct][3];
    }
    __syncthreads();

    float* dst = g_Dp + (size_t)s * PSZ + (size_t)b * CCH * HW;
#pragma unroll
    for (int i = t; i < 128 * CCH; i += 256) {
        const int c = i >> 7, n = i & 127;
        dst[(size_t)c * HW + n0 + n] = sD[n * OSTR + c];
    }
}

// ---------------------------------------------------------------------------
// Kernel 5: combine split partials + gamma + residual (vectorized)
// ---------------------------------------------------------------------------
__global__ __launch_bounds__(256) void combine_kernel(
    const float* __restrict__ x,
    const float* __restrict__ gamma,
    float* __restrict__ out)
{
    const size_t i = ((size_t)blockIdx.x * 256 + threadIdx.x) * 4;
    const float gm = gamma[0] * (1.0f / 4096.0f);
    float4 a = *(const float4*)(g_Dp + i);
    float4 c = *(const float4*)(g_Dp + PSZ + i);
    float4 d = *(const float4*)(g_Dp + 2 * (size_t)PSZ + i);
    float4 e = *(const float4*)(g_Dp + 3 * (size_t)PSZ + i);
    float4 xv = *(const float4*)(x + i);
    float4 o;
    o.x = gm * ((a.x + c.x) + (d.x + e.x)) + xv.x;
    o.y = gm * ((a.y + c.y) + (d.y + e.y)) + xv.y;
    o.z = gm * ((a.z + c.z) + (d.z + e.z)) + xv.z;
    o.w = gm * ((a.w + c.w) + (d.w + e.w)) + xv.w;
    *(float4*)(out + i) = o;
}

// ---------------------------------------------------------------------------
extern "C" void kernel_launch(void* const* d_in, const int* in_sizes, int n_in,
                              void* d_out, int out_size)
{
    const float* x     = (const float*)d_in[0];
    const float* Wq    = (const float*)d_in[1];
    const float* bq    = (const float*)d_in[2];
    const float* Wk    = (const float*)d_in[3];
    const float* bk    = (const float*)d_in[4];
    const float* Wv    = (const float*)d_in[5];
    const float* bv    = (const float*)d_in[6];
    const float* gamma = (const float*)d_in[7];
    float* out = (float*)d_out;

    qkv_kernel<<<dim3(HW / 128, NBAT), 512>>>(x, Wq, bq, Wk, bk, Wv, bv);
    denom_kernel<<<dim3(HW / 128, NSPL, NBAT), 256>>>();
    vscale_kernel<<<dim3(HW / 256, NBAT), 256>>>();
    attn_kernel<<<dim3(HW / 128, NS, NBAT), 256>>>();
    combine_kernel<<<PSZ / 1024, 256>>>(x, gamma, out);
}